// round 2
// baseline (speedup 1.0000x reference)
#include <cuda_runtime.h>
#include <cstdint>

// Problem shapes (fixed by the dataset)
#define BB 4
#define TE 512
#define TD 256
#define DE 512
#define DD 512
#define UU 128

// Scratch for projected tensors (allocation-free rule: __device__ globals)
__device__ float g_enc_p[BB * TE * UU];   // [B,Te,U]  1 MB
__device__ float g_dec_p[BB * TD * UU];   // [B,Td,U]  0.5 MB

__device__ __forceinline__ float ftanh(float x) {
    float r;
    asm("tanh.approx.f32 %0, %1;" : "=f"(r) : "f"(x));
    return r;
}

// ---------------------------------------------------------------------------
// Projection: Y[row,u] = sum_d X[row,d] * W[d,u] + bias[u]
// D = 512, U = 128. One warp per row; lane handles u = lane*4..lane*4+3.
// ---------------------------------------------------------------------------
__global__ void proj_kernel(const float* __restrict__ X,
                            const float* __restrict__ W,
                            const float* __restrict__ bias,
                            float* __restrict__ Y) {
    int warp = threadIdx.x >> 5;
    int lane = threadIdx.x & 31;
    int row  = blockIdx.x * 8 + warp;

    const float4* __restrict__ Xr = reinterpret_cast<const float4*>(X + (size_t)row * 512);
    const float4* __restrict__ W4 = reinterpret_cast<const float4*>(W);

    float4 acc = make_float4(0.f, 0.f, 0.f, 0.f);
    #pragma unroll 4
    for (int d4 = 0; d4 < 128; ++d4) {
        float4 xv = Xr[d4];                 // broadcast (same addr per warp)
        int d = d4 * 4;
        float4 w0 = W4[(d + 0) * 32 + lane];
        float4 w1 = W4[(d + 1) * 32 + lane];
        float4 w2 = W4[(d + 2) * 32 + lane];
        float4 w3 = W4[(d + 3) * 32 + lane];
        acc.x += xv.x * w0.x + xv.y * w1.x + xv.z * w2.x + xv.w * w3.x;
        acc.y += xv.x * w0.y + xv.y * w1.y + xv.z * w2.y + xv.w * w3.y;
        acc.z += xv.x * w0.z + xv.y * w1.z + xv.z * w2.z + xv.w * w3.z;
        acc.w += xv.x * w0.w + xv.y * w1.w + xv.z * w2.w + xv.w * w3.w;
    }
    float4 bv = reinterpret_cast<const float4*>(bias)[lane];
    acc.x += bv.x; acc.y += bv.y; acc.z += bv.z; acc.w += bv.w;
    reinterpret_cast<float4*>(Y + (size_t)row * 128)[lane] = acc;
}

// ---------------------------------------------------------------------------
// Fused score + tanh + softmax.
// Block: 256 threads (8 warps). Handles 8 t-rows of one batch (warp w -> row t0+w).
// For each 32-wide chunk of e, stage enc_p rows in padded shared; each thread
// computes score(t_local, e) with a full 128-u loop (float4 LDS, tanh.approx).
// Softmax is warp-local (row per warp). Writes normalized weights to `attn`.
// ---------------------------------------------------------------------------
__global__ void attn_kernel(const float* __restrict__ Vw,
                            float* __restrict__ attn) {
    __shared__ float enc_sh[32 * 132];   // 32 e-rows, pitch 132 floats (conflict-free)
    __shared__ float dec_sh[8 * 128];
    __shared__ float V_sh[128];

    int b  = blockIdx.y;
    int t0 = blockIdx.x * 8;
    int tid = threadIdx.x;
    int tl = tid >> 5;    // t_local / warp id
    int el = tid & 31;    // e lane

    // stage dec rows + V
    {
        const float4* dp = reinterpret_cast<const float4*>(g_dec_p + ((size_t)b * TD + t0) * 128);
        reinterpret_cast<float4*>(dec_sh)[tid] = dp[tid];   // 256 float4 = 8*128 floats
        if (tid < 32)
            reinterpret_cast<float4*>(V_sh)[tid] = reinterpret_cast<const float4*>(Vw)[tid];
    }

    float sc[16];
    float mx = -1e30f;

    #pragma unroll 1
    for (int c = 0; c < 16; ++c) {
        __syncthreads();   // previous chunk fully consumed (also covers dec/V stage)
        // stage enc_p chunk: 32 rows x 128 floats
        const float4* ep = reinterpret_cast<const float4*>(g_enc_p + ((size_t)b * TE + c * 32) * 128);
        #pragma unroll
        for (int k = 0; k < 4; ++k) {
            int idx = tid + k * 256;          // 0..1023
            int e  = idx >> 5;
            int u4 = idx & 31;
            *reinterpret_cast<float4*>(&enc_sh[e * 132 + u4 * 4]) = ep[e * 32 + u4];
        }
        __syncthreads();

        const float4* er = reinterpret_cast<const float4*>(&enc_sh[el * 132]);
        const float4* dr = reinterpret_cast<const float4*>(&dec_sh[tl * 128]);
        const float4* vr = reinterpret_cast<const float4*>(V_sh);
        float s = 0.f;
        #pragma unroll
        for (int u4 = 0; u4 < 32; ++u4) {
            float4 ev = er[u4];
            float4 dv = dr[u4];
            float4 vv = vr[u4];
            s += vv.x * ftanh(ev.x + dv.x);
            s += vv.y * ftanh(ev.y + dv.y);
            s += vv.z * ftanh(ev.z + dv.z);
            s += vv.w * ftanh(ev.w + dv.w);
        }
        sc[c] = s;
        mx = fmaxf(mx, s);
    }

    // warp-level softmax over the 512 scores of row t0+tl
    #pragma unroll
    for (int o = 16; o; o >>= 1) mx = fmaxf(mx, __shfl_xor_sync(0xffffffffu, mx, o));
    float sum = 0.f;
    #pragma unroll
    for (int c = 0; c < 16; ++c) { float e = __expf(sc[c] - mx); sc[c] = e; sum += e; }
    #pragma unroll
    for (int o = 16; o; o >>= 1) sum += __shfl_xor_sync(0xffffffffu, sum, o);
    float inv = __fdividef(1.f, sum);

    float* arow = attn + ((size_t)b * TD + t0 + tl) * TE;
    #pragma unroll
    for (int c = 0; c < 16; ++c) arow[c * 32 + el] = sc[c] * inv;
}

// ---------------------------------------------------------------------------
// Context GEMM: ctx[b,t,d] = sum_e attn[b,t,e] * enc[b,e,d]
// M=256(t), N=512(d), K=512(e), batch=4. Tile 32x64, K-chunk 32.
// 256 threads; each computes a 2(t) x 4(d) micro-tile.
// ---------------------------------------------------------------------------
__global__ void ctx_kernel(const float* __restrict__ attn,
                           const float* __restrict__ enc,
                           float* __restrict__ ctx) {
    __shared__ float As[32][36];   // attn tile (pad to 36 -> 144B rows, float4-aligned)
    __shared__ float Bs[32][64];   // enc tile

    int b  = blockIdx.z;
    int t0 = blockIdx.x * 32;
    int d0 = blockIdx.y * 64;
    int tid = threadIdx.x;
    int tx = tid & 15;     // d group (4 floats)
    int ty = tid >> 4;     // t rows ty and ty+16

    float4 acc0 = make_float4(0.f, 0.f, 0.f, 0.f);
    float4 acc1 = make_float4(0.f, 0.f, 0.f, 0.f);

    for (int e0 = 0; e0 < 512; e0 += 32) {
        __syncthreads();
        // load As: 32t x 32e
        {
            int i  = tid >> 3;
            int j4 = tid & 7;
            *reinterpret_cast<float4*>(&As[i][j4 * 4]) =
                *reinterpret_cast<const float4*>(&attn[((size_t)b * TD + t0 + i) * TE + e0 + j4 * 4]);
        }
        // load Bs: 32e x 64d (2 float4 per thread)
        #pragma unroll
        for (int r = 0; r < 2; ++r) {
            int idx = tid + r * 256;
            int k  = idx >> 4;
            int d4 = idx & 15;
            *reinterpret_cast<float4*>(&Bs[k][d4 * 4]) =
                *reinterpret_cast<const float4*>(&enc[((size_t)b * TE + e0 + k) * DE + d0 + d4 * 4]);
        }
        __syncthreads();

        #pragma unroll
        for (int k = 0; k < 32; ++k) {
            float a0 = As[ty][k];
            float a1 = As[ty + 16][k];
            float4 bv = *reinterpret_cast<const float4*>(&Bs[k][tx * 4]);
            acc0.x += a0 * bv.x; acc0.y += a0 * bv.y; acc0.z += a0 * bv.z; acc0.w += a0 * bv.w;
            acc1.x += a1 * bv.x; acc1.y += a1 * bv.y; acc1.z += a1 * bv.z; acc1.w += a1 * bv.w;
        }
    }

    float* o0 = ctx + ((size_t)b * TD + t0 + ty) * DE + d0 + tx * 4;
    float* o1 = ctx + ((size_t)b * TD + t0 + ty + 16) * DE + d0 + tx * 4;
    *reinterpret_cast<float4*>(o0) = acc0;
    *reinterpret_cast<float4*>(o1) = acc1;
}

// ---------------------------------------------------------------------------
extern "C" void kernel_launch(void* const* d_in, const int* in_sizes, int n_in,
                              void* d_out, int out_size) {
    const float* enc = (const float*)d_in[0];   // [4,512,512]
    const float* dec = (const float*)d_in[1];   // [4,256,512]
    const float* W1w = (const float*)d_in[2];   // [512,128]
    const float* W1b = (const float*)d_in[3];   // [128]
    const float* W2w = (const float*)d_in[4];   // [512,128]
    const float* W2b = (const float*)d_in[5];   // [128]
    const float* Vw  = (const float*)d_in[6];   // [128,1]
    // d_in[7] = V_b: softmax-invariant, unused.

    float* out  = (float*)d_out;
    float* ctx  = out;                          // [4,256,512]
    float* attn = out + (size_t)BB * TD * DE;   // [4,256,512]

    float* encp = nullptr;
    float* decp = nullptr;
    cudaGetSymbolAddress((void**)&encp, g_enc_p);
    cudaGetSymbolAddress((void**)&decp, g_dec_p);

    proj_kernel<<<(BB * TE) / 8, 256>>>(enc, W1w, W1b, encp);
    proj_kernel<<<(BB * TD) / 8, 256>>>(dec, W2w, W2b, decp);
    attn_kernel<<<dim3(TD / 8, BB), 256>>>(Vw, attn);
    ctx_kernel<<<dim3(TD / 32, DE / 64, BB), 256>>>(attn, enc, ctx);
}

// round 5
// speedup vs baseline: 1.4566x; 1.4566x over previous
#include <cuda_runtime.h>
#include <cstdint>

#define BB 4
#define TE 512
#define TD 256
#define DE 512
#define UU 128

// Scratch (allocation-free rule: __device__ globals)
__device__ float g_enc_p[BB * TE * UU];   // [B,Te,U]
__device__ float g_dec_p[BB * TD * UU];   // [B,Td,U]

__device__ __forceinline__ float ftanh(float x) {
    float r;
    asm("tanh.approx.f32 %0, %1;" : "=f"(r) : "f"(x));
    return r;
}

// ---------------------------------------------------------------------------
// Fused projection GEMM for BOTH enc and dec.
// Virtual rows: [0,2048) = enc rows, [2048,3072) = dec rows. K=512, N=128.
// Tile: 32 rows x 64 u, k-chunk 32. 128 threads, micro-tile 4x4.
// Grid: (96, 2) = 192 blocks.
// ---------------------------------------------------------------------------
__global__ void proj_kernel(const float* __restrict__ enc,
                            const float* __restrict__ dec,
                            const float* __restrict__ W1w, const float* __restrict__ W1b,
                            const float* __restrict__ W2w, const float* __restrict__ W2b,
                            float* __restrict__ encp, float* __restrict__ decp) {
    __shared__ float Xs[32][36];   // [k][row], padded
    __shared__ float Ws[32][64];   // [k][u]

    int r0 = blockIdx.x * 32;
    int u0 = blockIdx.y * 64;
    bool is_enc = (r0 < 2048);
    const float* __restrict__ X    = is_enc ? enc + (size_t)r0 * 512
                                            : dec + (size_t)(r0 - 2048) * 512;
    const float* __restrict__ W    = is_enc ? W1w : W2w;
    const float* __restrict__ bias = is_enc ? W1b : W2b;
    float* __restrict__ Y          = is_enc ? encp + (size_t)r0 * 128
                                            : decp + (size_t)(r0 - 2048) * 128;

    int tid = threadIdx.x;
    int tx = tid & 15;    // u group (4 u)
    int ty = tid >> 4;    // row group (4 rows)

    float4 acc[4];
    #pragma unroll
    for (int i = 0; i < 4; ++i) acc[i] = make_float4(0.f, 0.f, 0.f, 0.f);

    for (int k0 = 0; k0 < 512; k0 += 32) {
        __syncthreads();
        // stage X: 32 rows x 32 k (transpose to [k][row])
        #pragma unroll
        for (int r = 0; r < 2; ++r) {
            int idx = tid + r * 128;
            int row = idx >> 3, k4 = idx & 7;
            float4 v = *reinterpret_cast<const float4*>(&X[(size_t)row * 512 + k0 + k4 * 4]);
            Xs[k4 * 4 + 0][row] = v.x;
            Xs[k4 * 4 + 1][row] = v.y;
            Xs[k4 * 4 + 2][row] = v.z;
            Xs[k4 * 4 + 3][row] = v.w;
        }
        // stage W: 32 k x 64 u
        #pragma unroll
        for (int r = 0; r < 4; ++r) {
            int idx = tid + r * 128;
            int k = idx >> 4, u4 = idx & 15;
            *reinterpret_cast<float4*>(&Ws[k][u4 * 4]) =
                *reinterpret_cast<const float4*>(&W[(size_t)(k0 + k) * 128 + u0 + u4 * 4]);
        }
        __syncthreads();

        #pragma unroll
        for (int k = 0; k < 32; ++k) {
            float4 a = *reinterpret_cast<const float4*>(&Xs[k][ty * 4]);
            float4 b = *reinterpret_cast<const float4*>(&Ws[k][tx * 4]);
            acc[0].x += a.x * b.x; acc[0].y += a.x * b.y; acc[0].z += a.x * b.z; acc[0].w += a.x * b.w;
            acc[1].x += a.y * b.x; acc[1].y += a.y * b.y; acc[1].z += a.y * b.z; acc[1].w += a.y * b.w;
            acc[2].x += a.z * b.x; acc[2].y += a.z * b.y; acc[2].z += a.z * b.z; acc[2].w += a.z * b.w;
            acc[3].x += a.w * b.x; acc[3].y += a.w * b.y; acc[3].z += a.w * b.z; acc[3].w += a.w * b.w;
        }
    }

    float4 bv = *reinterpret_cast<const float4*>(&bias[u0 + tx * 4]);
    #pragma unroll
    for (int i = 0; i < 4; ++i) {
        acc[i].x += bv.x; acc[i].y += bv.y; acc[i].z += bv.z; acc[i].w += bv.w;
        *reinterpret_cast<float4*>(&Y[(size_t)(ty * 4 + i) * 128 + u0 + tx * 4]) = acc[i];
    }
}

// ---------------------------------------------------------------------------
// Fused score + tanh + softmax.
// Block: 256 threads (8 warps), 8 t-rows of one batch (warp w -> row t0+w).
// enc_p staged in 2 macro-chunks of 256 e-rows (dynamic smem, pitch 132);
// each thread accumulates 8 e-scores per macro-chunk, amortizing dv/vv loads.
// MUFU (tanh.approx) is the binding pipe.
// ---------------------------------------------------------------------------
#define ENC_PITCH 132
#define DEC_OFF   (256 * ENC_PITCH)          // 33792
#define V_OFF     (DEC_OFF + 8 * 128)        // 34816
#define ATTN_SMEM ((V_OFF + 128) * 4)        // 139776 bytes

__global__ void attn_kernel(const float* __restrict__ Vw,
                            float* __restrict__ attn) {
    extern __shared__ float sm[];
    float* enc_sh = sm;
    float* dec_sh = sm + DEC_OFF;
    float* V_sh   = sm + V_OFF;

    int b  = blockIdx.y;
    int t0 = blockIdx.x * 8;
    int tid = threadIdx.x;
    int tl = tid >> 5;    // warp / t_local
    int el = tid & 31;    // e lane

    // stage dec rows + V
    {
        const float4* dp = reinterpret_cast<const float4*>(g_dec_p + ((size_t)b * TD + t0) * 128);
        reinterpret_cast<float4*>(dec_sh)[tid] = dp[tid];
        if (tid < 32)
            reinterpret_cast<float4*>(V_sh)[tid] = reinterpret_cast<const float4*>(Vw)[tid];
    }

    float sc[16];
    float mx = -1e30f;

    #pragma unroll
    for (int m = 0; m < 2; ++m) {
        __syncthreads();
        // stage 256 e-rows of enc_p (pitch 132 -> conflict-free LDS.128)
        const float4* ep = reinterpret_cast<const float4*>(
            g_enc_p + ((size_t)b * TE + m * 256) * 128);
        #pragma unroll
        for (int r = 0; r < 32; ++r) {
            int idx = tid + r * 256;
            int e = idx >> 5, u4 = idx & 31;
            *reinterpret_cast<float4*>(&enc_sh[e * ENC_PITCH + u4 * 4]) = ep[idx];
        }
        __syncthreads();

        float a[8];
        #pragma unroll
        for (int j = 0; j < 8; ++j) a[j] = 0.f;

        const float4* dr = reinterpret_cast<const float4*>(&dec_sh[tl * 128]);
        const float4* vr = reinterpret_cast<const float4*>(V_sh);

        #pragma unroll 4
        for (int u4 = 0; u4 < 32; ++u4) {
            float4 dv = dr[u4];
            float4 vv = vr[u4];
            #pragma unroll
            for (int j = 0; j < 8; ++j) {
                float4 ev = *reinterpret_cast<const float4*>(
                    &enc_sh[(el + 32 * j) * ENC_PITCH + u4 * 4]);
                a[j] += vv.x * ftanh(ev.x + dv.x);
                a[j] += vv.y * ftanh(ev.y + dv.y);
                a[j] += vv.z * ftanh(ev.z + dv.z);
                a[j] += vv.w * ftanh(ev.w + dv.w);
            }
        }
        #pragma unroll
        for (int j = 0; j < 8; ++j) {
            sc[m * 8 + j] = a[j];
            mx = fmaxf(mx, a[j]);
        }
    }

    // warp-level softmax over 512 scores of row t0+tl (score at chunk c: e = c*32+el)
    #pragma unroll
    for (int o = 16; o; o >>= 1) mx = fmaxf(mx, __shfl_xor_sync(0xffffffffu, mx, o));
    float sum = 0.f;
    #pragma unroll
    for (int c = 0; c < 16; ++c) { float e = __expf(sc[c] - mx); sc[c] = e; sum += e; }
    #pragma unroll
    for (int o = 16; o; o >>= 1) sum += __shfl_xor_sync(0xffffffffu, sum, o);
    float inv = __fdividef(1.f, sum);

    float* arow = attn + ((size_t)b * TD + t0 + tl) * TE;
    #pragma unroll
    for (int c = 0; c < 16; ++c) arow[c * 32 + el] = sc[c] * inv;
}

// ---------------------------------------------------------------------------
// Context GEMM: ctx[b,t,d] = sum_e attn[b,t,e] * enc[b,e,d]
// 64x64 tile, k-chunk 32, 128 threads, micro-tile 8(t) x 4(d).
// Grid (4, 8, 4) = 128 blocks. FMA-bound.
// ---------------------------------------------------------------------------
__global__ void ctx_kernel(const float* __restrict__ attn,
                           const float* __restrict__ enc,
                           float* __restrict__ ctx) {
    __shared__ float As[32][68];   // [e][t], padded, 16B-aligned rows
    __shared__ float Bs[32][64];   // [e][d]

    int b  = blockIdx.z;
    int t0 = blockIdx.x * 64;
    int d0 = blockIdx.y * 64;
    int tid = threadIdx.x;
    int tx = tid & 15;    // d group (4 d)
    int ty = tid >> 4;    // t group (8 t: ty*8..)

    float4 acc[8];
    #pragma unroll
    for (int i = 0; i < 8; ++i) acc[i] = make_float4(0.f, 0.f, 0.f, 0.f);

    for (int e0 = 0; e0 < 512; e0 += 32) {
        __syncthreads();
        // stage As: 64 t x 32 e, transposed to [e][t]
        #pragma unroll
        for (int r = 0; r < 4; ++r) {
            int idx = tid + r * 128;
            int i = idx >> 3, j4 = idx & 7;
            float4 v = *reinterpret_cast<const float4*>(
                &attn[((size_t)b * TD + t0 + i) * TE + e0 + j4 * 4]);
            As[j4 * 4 + 0][i] = v.x;
            As[j4 * 4 + 1][i] = v.y;
            As[j4 * 4 + 2][i] = v.z;
            As[j4 * 4 + 3][i] = v.w;
        }
        // stage Bs: 32 e x 64 d
        #pragma unroll
        for (int r = 0; r < 4; ++r) {
            int idx = tid + r * 128;
            int k = idx >> 4, d4 = idx & 15;
            *reinterpret_cast<float4*>(&Bs[k][d4 * 4]) =
                *reinterpret_cast<const float4*>(
                    &enc[((size_t)b * TE + e0 + k) * DE + d0 + d4 * 4]);
        }
        __syncthreads();

        #pragma unroll
        for (int k = 0; k < 32; ++k) {
            float4 bv = *reinterpret_cast<const float4*>(&Bs[k][tx * 4]);
            float4 a0 = *reinterpret_cast<const float4*>(&As[k][ty * 8]);
            float4 a1 = *reinterpret_cast<const float4*>(&As[k][ty * 8 + 4]);
            acc[0].x += a0.x * bv.x; acc[0].y += a0.x * bv.y; acc[0].z += a0.x * bv.z; acc[0].w += a0.x * bv.w;
            acc[1].x += a0.y * bv.x; acc[1].y += a0.y * bv.y; acc[1].z += a0.y * bv.z; acc[1].w += a0.y * bv.w;
            acc[2].x += a0.z * bv.x; acc[2].y += a0.z * bv.y; acc[2].z += a0.z * bv.z; acc[2].w += a0.z * bv.w;
            acc[3].x += a0.w * bv.x; acc[3].y += a0.w * bv.y; acc[3].z += a0.w * bv.z; acc[3].w += a0.w * bv.w;
            acc[4].x += a1.x * bv.x; acc[4].y += a1.x * bv.y; acc[4].z += a1.x * bv.z; acc[4].w += a1.x * bv.w;
            acc[5].x += a1.y * bv.x; acc[5].y += a1.y * bv.y; acc[5].z += a1.y * bv.z; acc[5].w += a1.y * bv.w;
            acc[6].x += a1.z * bv.x; acc[6].y += a1.z * bv.y; acc[6].z += a1.z * bv.z; acc[6].w += a1.z * bv.w;
            acc[7].x += a1.w * bv.x; acc[7].y += a1.w * bv.y; acc[7].z += a1.w * bv.z; acc[7].w += a1.w * bv.w;
        }
    }

    #pragma unroll
    for (int i = 0; i < 8; ++i) {
        *reinterpret_cast<float4*>(
            &ctx[((size_t)b * TD + t0 + ty * 8 + i) * DE + d0 + tx * 4]) = acc[i];
    }
}

// ---------------------------------------------------------------------------
extern "C" void kernel_launch(void* const* d_in, const int* in_sizes, int n_in,
                              void* d_out, int out_size) {
    const float* enc = (const float*)d_in[0];   // [4,512,512]
    const float* dec = (const float*)d_in[1];   // [4,256,512]
    const float* W1w = (const float*)d_in[2];   // [512,128]
    const float* W1b = (const float*)d_in[3];   // [128]
    const float* W2w = (const float*)d_in[4];   // [512,128]
    const float* W2b = (const float*)d_in[5];   // [128]
    const float* Vw  = (const float*)d_in[6];   // [128,1]
    // d_in[7] = V_b: softmax-invariant, unused.

    float* out  = (float*)d_out;
    float* ctx  = out;                          // [4,256,512]
    float* attn = out + (size_t)BB * TD * DE;   // [4,256,512]

    float* encp = nullptr;
    float* decp = nullptr;
    cudaGetSymbolAddress((void**)&encp, g_enc_p);
    cudaGetSymbolAddress((void**)&decp, g_dec_p);

    cudaFuncSetAttribute(attn_kernel,
                         cudaFuncAttributeMaxDynamicSharedMemorySize, ATTN_SMEM);

    proj_kernel<<<dim3(96, 2), 128>>>(enc, dec, W1w, W1b, W2w, W2b, encp, decp);
    attn_kernel<<<dim3(TD / 8, BB), 256, ATTN_SMEM>>>(Vw, attn);
    ctx_kernel<<<dim3(TD / 64, DE / 64, BB), 128>>>(attn, enc, ctx);
}